// round 11
// baseline (speedup 1.0000x reference)
#include <cuda_runtime.h>
#include <cub/block/block_radix_sort.cuh>

namespace rpn {

constexpr int NMS_NT   = 512;
constexpr int NMS_IPT  = 4;
constexpr int CAND_CAP = NMS_NT * NMS_IPT;   // 2048 candidates per batch
constexpr int SEL_TARGET = 1300;             // min candidates above threshold
constexpr int IDXBITS  = 18;                 // N = 262144 = 2^18
constexpr unsigned IDXMASK = (1u << IDXBITS) - 1u;
constexpr int MAXBN = 1 << 21;
constexpr int MAXB  = 8;
constexpr int NBINS = 4096;                  // 12-bit histogram of sort key
constexpr int GSZ   = 64;                    // candidates resolved per phase
constexpr int WORDS = CAND_CAP / 64;         // 32 u64 words per mask row

// ---- device scratch (static __device__ arrays; no allocation anywhere) ----
__device__ unsigned           g_keys[MAXBN];
__device__ unsigned           g_hist[MAXB * NBINS];   // zero-init at load;
__device__ int                g_counts[MAXB];         // re-zeroed each run
__device__ unsigned           g_thresh[MAXB];
__device__ unsigned long long g_cand[MAXB * CAND_CAP];
__device__ unsigned long long g_sorted[MAXB * CAND_CAP];
__device__ float4             g_cbox[MAXB * CAND_CAP];
__device__ float              g_c7[MAXB * CAND_CAP];
__device__ unsigned long long g_mask[MAXB * CAND_CAP * WORDS];  // 4MB

// Shared box math -> identical codegen in decode and sort (R7-verified exact)
__device__ __forceinline__ float4 decode_box(float4 a, float4 d,
                                             float W, float H) {
  const float LOG_MAX = 4.135166556742356f;  // log(1000/16)
  float aw = a.z - a.x, ah = a.w - a.y;
  float acx = a.x + 0.5f * aw, acy = a.y + 0.5f * ah;
  float dw = fminf(d.z, LOG_MAX), dh = fminf(d.w, LOG_MAX);
  float pcx = d.x * aw + acx, pcy = d.y * ah + acy;
  float pw = expf(dw) * aw, ph = expf(dh) * ah;
  float x1 = fminf(fmaxf(pcx - 0.5f * pw, 0.0f), W);
  float y1 = fminf(fmaxf(pcy - 0.5f * ph, 0.0f), H);
  float x2 = fminf(fmaxf(pcx + 0.5f * pw, 0.0f), W);
  float y2 = fminf(fmaxf(pcy + 0.5f * ph, 0.0f), H);
  return make_float4(x1, y1, x2, y2);
}

// ---------------------------------------------------------------- decode ---
// No g_boxes store: traffic 44MB -> 28MB. Boxes re-decoded in sort_kernel.
__device__ __forceinline__ void decode_one(const float4* __restrict__ anchors,
                                           const float4* __restrict__ deltas,
                                           const float*  __restrict__ obj,
                                           unsigned* __restrict__ hloc,
                                           int b, int n, int N,
                                           float W, float H) {
  float4 bx = decode_box(anchors[n], deltas[b * N + n], W, H);
  float  o = obj[b * N + n];
  float area = (bx.z - bx.x) * (bx.w - bx.y);
  float s = (area > 1.0f) ? o : __int_as_float(0xff800000);  // -inf
  unsigned ub  = __float_as_uint(s);
  unsigned key = (ub & 0x80000000u) ? ~ub : (ub | 0x80000000u);  // monotone
  g_keys[b * N + n] = key;
  atomicAdd(&hloc[key >> 20], 1u);
}

__global__ void decode_kernel(const float4* __restrict__ anchors,
                              const float4* __restrict__ deltas,
                              const float*  __restrict__ obj,
                              const int*    __restrict__ imh,
                              const int*    __restrict__ imw,
                              int N) {
  __shared__ unsigned hloc[NBINS];
  const int b   = blockIdx.y;
  const int tid = threadIdx.x;
  for (int i = tid; i < NBINS; i += blockDim.x) hloc[i] = 0u;
  __syncthreads();

  const float W = (float)(*imw);
  const float H = (float)(*imh);
  const int stride = gridDim.x * blockDim.x;

  for (int n = blockIdx.x * blockDim.x + tid; n < N; n += 2 * stride) {
    decode_one(anchors, deltas, obj, hloc, b, n, N, W, H);
    int n2 = n + stride;
    if (n2 < N) decode_one(anchors, deltas, obj, hloc, b, n2, N, W, H);
  }
  __syncthreads();
  for (int i = tid; i < NBINS; i += blockDim.x) {
    unsigned v = hloc[i];
    if (v) atomicAdd(&g_hist[b * NBINS + i], v);
  }
}

// ------------------------------------------------------------- threshold ---
// Also re-zeroes g_hist (already held in registers) and g_counts for the
// next graph replay -> init_kernel deleted.
__global__ __launch_bounds__(1024) void threshold_kernel(int target) {
  const int b = blockIdx.x;
  const int tid = threadIdx.x;
  const int lane = tid & 31, w = tid >> 5;
  const unsigned full = 0xffffffffu;
  __shared__ unsigned wtot[32];
  __shared__ unsigned wafter[32];
  __shared__ int best;

  unsigned h[4];
#pragma unroll
  for (int i = 0; i < 4; i++) h[i] = g_hist[b * NBINS + tid * 4 + i];
  // re-zero for next replay (we own these 4 bins)
  *(uint4*)&g_hist[b * NBINS + tid * 4] = make_uint4(0, 0, 0, 0);
  if (tid == 0) g_counts[b] = 0;
  unsigned mysum = h[0] + h[1] + h[2] + h[3];

  unsigned s = mysum;
#pragma unroll
  for (int off = 1; off < 32; off <<= 1) {
    unsigned v = __shfl_down_sync(full, s, off);
    if (lane + off < 32) s += v;
  }
  if (lane == 0) wtot[w] = s;
  if (tid == 0) best = 0;
  __syncthreads();

  if (w == 0) {
    unsigned t = wtot[lane];
    unsigned si = t;
#pragma unroll
    for (int off = 1; off < 32; off <<= 1) {
      unsigned v = __shfl_down_sync(full, si, off);
      if (lane + off < 32) si += v;
    }
    wafter[lane] = si - t;                 // sum of warps > lane
  }
  __syncthreads();

  unsigned after = (s - mysum) + wafter[w];  // sum over threads > tid
  unsigned run = after;
  int loc = -1;
  for (int i = 3; i >= 0; i--) {
    run += h[i];
    if (loc < 0 && run >= (unsigned)target) loc = tid * 4 + i;
  }
  if (loc >= 0) atomicMax(&best, loc);
  __syncthreads();
  if (tid == 0) g_thresh[b] = ((unsigned)best) << 20;
}

// --------------------------------------------------------------- compact ---
__global__ void compact_kernel(int N) {
  const int b    = blockIdx.y;
  const int tid  = threadIdx.x;
  const int base = (blockIdx.x * blockDim.x + tid) * 4;
  __shared__ int wsum[8];
  __shared__ int sbase;

  const unsigned thr = g_thresh[b];
  uint4 kv = make_uint4(0, 0, 0, 0);
  if (base + 3 < N) {
    kv = *(const uint4*)&g_keys[b * N + base];
  } else if (base < N) {
    kv.x = g_keys[b * N + base];
    if (base + 1 < N) kv.y = g_keys[b * N + base + 1];
    if (base + 2 < N) kv.z = g_keys[b * N + base + 2];
  }
  bool p0 = kv.x >= thr, p1 = kv.y >= thr, p2 = kv.z >= thr, p3 = kv.w >= thr;
  int cnt = (int)p0 + (int)p1 + (int)p2 + (int)p3;

  const unsigned full = 0xffffffffu;
  int lane = tid & 31, w = tid >> 5;
  int sc = cnt;
#pragma unroll
  for (int off = 1; off < 32; off <<= 1) {
    int v = __shfl_up_sync(full, sc, off);
    if (lane >= off) sc += v;
  }
  if (lane == 31) wsum[w] = sc;
  __syncthreads();
  if (tid == 0) {
    int tot = 0;
#pragma unroll
    for (int i = 0; i < 8; i++) { int c = wsum[i]; wsum[i] = tot; tot += c; }
    sbase = tot ? atomicAdd(&g_counts[b], tot) : 0;
  }
  __syncthreads();

  int offs = sbase + wsum[w] + (sc - cnt);
  unsigned long long* dst = &g_cand[b * CAND_CAP];
#define RPN_EMIT(P, KEY, NN)                                                \
  if (P) {                                                                  \
    if (offs < CAND_CAP)                                                    \
      dst[offs] = ((unsigned long long)(KEY) << IDXBITS) |                  \
                  (unsigned long long)(IDXMASK - (unsigned)(NN));           \
    offs++;                                                                 \
  }
  RPN_EMIT(p0, kv.x, base)
  RPN_EMIT(p1, kv.y, base + 1)
  RPN_EMIT(p2, kv.z, base + 2)
  RPN_EMIT(p3, kv.w, base + 3)
#undef RPN_EMIT
}

// ------------------------------------------------------------------ sort ---
// Sort candidates, then RE-DECODE their boxes (one-time, latency-overlapped;
// bit-identical math via decode_box) into sorted-order g_cbox/g_c7.
typedef cub::BlockRadixSort<unsigned long long, NMS_NT, NMS_IPT,
                            cub::NullType, 6> Sorter;

__global__ __launch_bounds__(NMS_NT, 1)
void sort_kernel(const float4* __restrict__ anchors,
                 const float4* __restrict__ deltas,
                 const int* __restrict__ imh,
                 const int* __restrict__ imw, int N) {
  __shared__ typename Sorter::TempStorage ts;
  const int b = blockIdx.x;
  const int tid = threadIdx.x;
  const int Creal = min(g_counts[b], CAND_CAP);
  const float W = (float)(*imw);
  const float H = (float)(*imh);

  unsigned long long tk[NMS_IPT];
#pragma unroll
  for (int i = 0; i < NMS_IPT; i++) {
    int slot = tid * NMS_IPT + i;
    tk[i] = (slot < Creal) ? g_cand[b * CAND_CAP + slot] : 0ull;
  }
  Sorter(ts).SortDescending(tk, 0, 32 + IDXBITS);
  // blocked: thread t holds sorted positions [4t, 4t+4)
#pragma unroll
  for (int i = 0; i < NMS_IPT; i++) {
    int slot = tid * NMS_IPT + i;
    g_sorted[b * CAND_CAP + slot] = tk[i];
    int idx = (int)(IDXMASK - (unsigned)(tk[i] & IDXMASK));
    float4 bx = decode_box(anchors[idx], deltas[b * N + idx], W, H);
    g_cbox[b * CAND_CAP + slot] = bx;
    g_c7[b * CAND_CAP + slot] = 0.7f * ((bx.z - bx.x) * (bx.w - bx.y) + 1e-9f);
  }
}

// ------------------------------------------------------------------ mask ---
// Full-chip pairwise suppression matrix over sorted candidates.
__global__ void mask_kernel() {
  const int w  = blockIdx.x;        // word 0..31
  const int rt = blockIdx.y;        // row tile (128 rows each)
  const int b  = blockIdx.z;
  const int tid = threadIdx.x;      // 128 threads

  __shared__ float4 cb[64];
  __shared__ float  cc[64];
  if (tid < 64) {
    int j = w * 64 + tid;
    cb[tid] = g_cbox[b * CAND_CAP + j];
    cc[tid] = g_c7[b * CAND_CAP + j];
  }
  __syncthreads();

  const int i = rt * 128 + tid;
  float4 A = g_cbox[b * CAND_CAP + i];
  float a7 = g_c7[b * CAND_CAP + i];

  unsigned long long word = 0ull;
  int j0min = i + 1 - w * 64;       // strict j > i
  if (j0min < 0) j0min = 0;
  for (int j0 = j0min; j0 < 64; j0++) {
    float4 C = cb[j0];
    float ix1 = fmaxf(A.x, C.x), iy1 = fmaxf(A.y, C.y);
    float ix2 = fminf(A.z, C.z), iy2 = fminf(A.w, C.w);
    float inter = fmaxf(ix2 - ix1, 0.0f) * fmaxf(iy2 - iy1, 0.0f);
    if (1.7f * inter > a7 + cc[j0]) word |= 1ull << j0;
  }
  g_mask[((size_t)b * CAND_CAP + i) * WORDS + w] = word;
}

// ------------------------------------------------------------------- nms ---
struct SmemNMS {
  unsigned long long pair[GSZ];
  unsigned           warpor[16][2];
  unsigned long long s_keep;
  int                s_cnt;
};

__device__ __forceinline__ int nth_set(unsigned long long m, int r) {
  unsigned lo = (unsigned)m;
  int c = __popc(lo);
  if (r < c) return (int)__fns(lo, 0, r + 1);
  return 32 + (int)__fns((unsigned)(m >> 32), 0, r - c + 1);
}

__global__ __launch_bounds__(NMS_NT, 1) void nms_kernel(float* __restrict__ out,
                                                        int K) {
  __shared__ SmemNMS sm;
  const int b = blockIdx.x;
  const int tid = threadIdx.x;
  const int lane = tid & 31, wrp = tid >> 5;
  const unsigned full = 0xffffffffu;

  const int Creal = min(g_counts[b], CAND_CAP);
  const unsigned long long* mbase = &g_mask[(size_t)b * CAND_CAP * WORDS];

  int kp0 = -1, kp1 = -1;
  int nkept = 0, pos = 0;

  while (nkept < K && pos < Creal) {
    const int G = min(GSZ, Creal - pos);
    const int gw = pos >> 6;

    unsigned long long flags = 0ull;
    if (tid < nkept)          flags  = mbase[(size_t)kp0 * WORDS + gw];
    if (NMS_NT + tid < nkept) flags |= mbase[(size_t)kp1 * WORDS + gw];
    unsigned wlo = __reduce_or_sync(full, (unsigned)flags);
    unsigned whi = __reduce_or_sync(full, (unsigned)(flags >> 32));
    if (lane == 0) { sm.warpor[wrp][0] = wlo; sm.warpor[wrp][1] = whi; }

    if (tid < G) sm.pair[tid] = mbase[(size_t)(pos + tid) * WORDS + gw];
    __syncthreads();

    if (wrp == 0) {
      unsigned l0 = (lane < 16) ? sm.warpor[lane][0] : 0u;
      unsigned h0 = (lane < 16) ? sm.warpor[lane][1] : 0u;
      unsigned long long sup =
          (unsigned long long)__reduce_or_sync(full, l0) |
          ((unsigned long long)__reduce_or_sync(full, h0) << 32);
      unsigned long long keep = 0ull, acc = 0ull;
      int cnt = 0;
      const int room = K - nkept;
      for (int g = 0; g < G; g++) {
        bool s = (((sup | acc) >> g) & 1ull) != 0ull;
        if (!s) {
          keep |= 1ull << g;
          acc |= sm.pair[g];
          if (++cnt >= room) break;
        }
      }
      if (lane == 0) { sm.s_keep = keep; sm.s_cnt = cnt; }
    }
    __syncthreads();

    const unsigned long long keep = sm.s_keep;
    const int cnt = sm.s_cnt;
    int r0 = tid - nkept;
    if (r0 >= 0 && r0 < cnt) kp0 = pos + nth_set(keep, r0);
    int r1 = NMS_NT + tid - nkept;
    if (r1 >= 0 && r1 < cnt) kp1 = pos + nth_set(keep, r1);

    nkept += cnt;
    pos += GSZ;
    __syncthreads();
  }

  if (tid < K) {
    float* o = out + ((size_t)b * K + tid) * 6;
    if (tid < nkept) {
      float4 bx = g_cbox[b * CAND_CAP + kp0];
      unsigned key = (unsigned)(g_sorted[b * CAND_CAP + kp0] >> IDXBITS);
      unsigned bits = (key & 0x80000000u) ? (key & 0x7fffffffu) : ~key;
      o[0] = bx.x; o[1] = bx.y; o[2] = bx.z; o[3] = bx.w;
      o[4] = __uint_as_float(bits); o[5] = 1.0f;
    } else {
      o[0] = 0.0f; o[1] = 0.0f; o[2] = 0.0f; o[3] = 0.0f;
      o[4] = 0.0f; o[5] = 0.0f;
    }
  }
  int t2 = tid + NMS_NT;
  if (t2 < K) {
    float* o = out + ((size_t)b * K + t2) * 6;
    if (t2 < nkept) {
      float4 bx = g_cbox[b * CAND_CAP + kp1];
      unsigned key = (unsigned)(g_sorted[b * CAND_CAP + kp1] >> IDXBITS);
      unsigned bits = (key & 0x80000000u) ? (key & 0x7fffffffu) : ~key;
      o[0] = bx.x; o[1] = bx.y; o[2] = bx.z; o[3] = bx.w;
      o[4] = __uint_as_float(bits); o[5] = 1.0f;
    } else {
      o[0] = 0.0f; o[1] = 0.0f; o[2] = 0.0f; o[3] = 0.0f;
      o[4] = 0.0f; o[5] = 0.0f;
    }
  }
}

}  // namespace rpn

extern "C" void kernel_launch(void* const* d_in, const int* in_sizes, int n_in,
                              void* d_out, int out_size) {
  using namespace rpn;
  const float4* anchors = (const float4*)d_in[0];
  const float4* deltas  = (const float4*)d_in[1];
  const float*  obj     = (const float*)d_in[2];
  const int*    imh     = (const int*)d_in[3];
  const int*    imw     = (const int*)d_in[4];

  int N = in_sizes[0] / 4;
  int B = (N > 0) ? in_sizes[2] / N : 0;
  if (B <= 0 || N <= 0) return;
  int K = out_size / (B * 6);
  if (K > 1024) K = 1024;

  dim3 dgrid(128, B);
  decode_kernel<<<dgrid, 256>>>(anchors, deltas, obj, imh, imw, N);

  threshold_kernel<<<B, 1024>>>(SEL_TARGET);

  dim3 cgrid((N + 1023) / 1024, B);
  compact_kernel<<<cgrid, 256>>>(N);

  sort_kernel<<<B, NMS_NT>>>(anchors, deltas, imh, imw, N);

  dim3 mgrid(WORDS, CAND_CAP / 128, B);
  mask_kernel<<<mgrid, 128>>>();

  nms_kernel<<<B, NMS_NT>>>((float*)d_out, K);
}

// round 12
// speedup vs baseline: 1.0196x; 1.0196x over previous
#include <cuda_runtime.h>
#include <cub/block/block_radix_sort.cuh>

namespace rpn {

constexpr int NMS_NT   = 512;
constexpr int NMS_IPT  = 4;
constexpr int CAND_CAP = NMS_NT * NMS_IPT;   // 2048 candidates per batch
constexpr int SEL_TARGET = 1300;             // min candidates above threshold
constexpr int IDXBITS  = 18;                 // N = 262144 = 2^18
constexpr unsigned IDXMASK = (1u << IDXBITS) - 1u;
constexpr int MAXBN = 1 << 21;
constexpr int MAXB  = 8;
constexpr int NBINS = 4096;                  // 12-bit histogram of sort key
constexpr int GSZ   = 64;                    // candidates resolved per phase
constexpr int WORDS = CAND_CAP / 64;         // 32 u64 words per mask row

// ---- device scratch (static __device__ arrays; no allocation anywhere) ----
__device__ unsigned           g_keys[MAXBN];
__device__ unsigned           g_hist[MAXB * NBINS];   // zero at load;
__device__ int                g_counts[MAXB];         // re-zeroed each run
__device__ unsigned           g_thresh[MAXB];
__device__ unsigned long long g_cand[MAXB * CAND_CAP];
__device__ unsigned long long g_sorted[MAXB * CAND_CAP];
__device__ float4             g_cbox[MAXB * CAND_CAP];
__device__ float              g_c7[MAXB * CAND_CAP];
__device__ unsigned long long g_mask[MAXB * CAND_CAP * WORDS];  // 4MB

// Shared box math -> identical codegen everywhere (R7-verified bit-exact)
__device__ __forceinline__ float4 decode_box(float4 a, float4 d,
                                             float W, float H) {
  const float LOG_MAX = 4.135166556742356f;  // log(1000/16)
  float aw = a.z - a.x, ah = a.w - a.y;
  float acx = a.x + 0.5f * aw, acy = a.y + 0.5f * ah;
  float dw = fminf(d.z, LOG_MAX), dh = fminf(d.w, LOG_MAX);
  float pcx = d.x * aw + acx, pcy = d.y * ah + acy;
  float pw = expf(dw) * aw, ph = expf(dh) * ah;
  float x1 = fminf(fmaxf(pcx - 0.5f * pw, 0.0f), W);
  float y1 = fminf(fmaxf(pcy - 0.5f * ph, 0.0f), H);
  float x2 = fminf(fmaxf(pcx + 0.5f * pw, 0.0f), W);
  float y2 = fminf(fmaxf(pcy + 0.5f * ph, 0.0f), H);
  return make_float4(x1, y1, x2, y2);
}

// ---------------------------------------------------------------- decode ---
__device__ __forceinline__ void decode_one(const float4* __restrict__ anchors,
                                           const float4* __restrict__ deltas,
                                           const float*  __restrict__ obj,
                                           unsigned* __restrict__ hloc,
                                           int b, int n, int N,
                                           float W, float H) {
  float4 bx = decode_box(anchors[n], deltas[b * N + n], W, H);
  float  o = obj[b * N + n];
  float area = (bx.z - bx.x) * (bx.w - bx.y);
  float s = (area > 1.0f) ? o : __int_as_float(0xff800000);  // -inf
  unsigned ub  = __float_as_uint(s);
  unsigned key = (ub & 0x80000000u) ? ~ub : (ub | 0x80000000u);  // monotone
  g_keys[b * N + n] = key;
  atomicAdd(&hloc[key >> 20], 1u);
}

__global__ void decode_kernel(const float4* __restrict__ anchors,
                              const float4* __restrict__ deltas,
                              const float*  __restrict__ obj,
                              const int*    __restrict__ imh,
                              const int*    __restrict__ imw,
                              int N) {
  __shared__ unsigned hloc[NBINS];
  const int b   = blockIdx.y;
  const int tid = threadIdx.x;
  for (int i = tid; i < NBINS; i += blockDim.x) hloc[i] = 0u;
  __syncthreads();

  const float W = (float)(*imw);
  const float H = (float)(*imh);
  const int stride = gridDim.x * blockDim.x;

  // 4 independent bodies in flight (MLP 4x)
  for (int n = blockIdx.x * blockDim.x + tid; n < N; n += 4 * stride) {
    decode_one(anchors, deltas, obj, hloc, b, n, N, W, H);
    int n1 = n + stride;
    if (n1 < N) decode_one(anchors, deltas, obj, hloc, b, n1, N, W, H);
    int n2 = n + 2 * stride;
    if (n2 < N) decode_one(anchors, deltas, obj, hloc, b, n2, N, W, H);
    int n3 = n + 3 * stride;
    if (n3 < N) decode_one(anchors, deltas, obj, hloc, b, n3, N, W, H);
  }
  __syncthreads();
  for (int i = tid; i < NBINS; i += blockDim.x) {
    unsigned v = hloc[i];
    if (v) atomicAdd(&g_hist[b * NBINS + i], v);
  }
}

// ------------------------------------------------------------- threshold ---
// Also re-zeroes g_hist / g_counts for the next graph replay.
__global__ __launch_bounds__(1024) void threshold_kernel(int target) {
  const int b = blockIdx.x;
  const int tid = threadIdx.x;
  const int lane = tid & 31, w = tid >> 5;
  const unsigned full = 0xffffffffu;
  __shared__ unsigned wtot[32];
  __shared__ unsigned wafter[32];
  __shared__ int best;

  unsigned h[4];
#pragma unroll
  for (int i = 0; i < 4; i++) h[i] = g_hist[b * NBINS + tid * 4 + i];
  *(uint4*)&g_hist[b * NBINS + tid * 4] = make_uint4(0, 0, 0, 0);
  if (tid == 0) g_counts[b] = 0;
  unsigned mysum = h[0] + h[1] + h[2] + h[3];

  unsigned s = mysum;
#pragma unroll
  for (int off = 1; off < 32; off <<= 1) {
    unsigned v = __shfl_down_sync(full, s, off);
    if (lane + off < 32) s += v;
  }
  if (lane == 0) wtot[w] = s;
  if (tid == 0) best = 0;
  __syncthreads();

  if (w == 0) {
    unsigned t = wtot[lane];
    unsigned si = t;
#pragma unroll
    for (int off = 1; off < 32; off <<= 1) {
      unsigned v = __shfl_down_sync(full, si, off);
      if (lane + off < 32) si += v;
    }
    wafter[lane] = si - t;                 // sum of warps > lane
  }
  __syncthreads();

  unsigned after = (s - mysum) + wafter[w];  // sum over threads > tid
  unsigned run = after;
  int loc = -1;
  for (int i = 3; i >= 0; i--) {
    run += h[i];
    if (loc < 0 && run >= (unsigned)target) loc = tid * 4 + i;
  }
  if (loc >= 0) atomicMax(&best, loc);
  __syncthreads();
  if (tid == 0) g_thresh[b] = ((unsigned)best) << 20;
}

// --------------------------------------------------------------- compact ---
__global__ void compact_kernel(int N) {
  const int b    = blockIdx.y;
  const int tid  = threadIdx.x;
  const int base = (blockIdx.x * blockDim.x + tid) * 4;
  __shared__ int wsum[8];
  __shared__ int sbase;

  const unsigned thr = g_thresh[b];
  uint4 kv = make_uint4(0, 0, 0, 0);
  if (base + 3 < N) {
    kv = *(const uint4*)&g_keys[b * N + base];
  } else if (base < N) {
    kv.x = g_keys[b * N + base];
    if (base + 1 < N) kv.y = g_keys[b * N + base + 1];
    if (base + 2 < N) kv.z = g_keys[b * N + base + 2];
  }
  bool p0 = kv.x >= thr, p1 = kv.y >= thr, p2 = kv.z >= thr, p3 = kv.w >= thr;
  int cnt = (int)p0 + (int)p1 + (int)p2 + (int)p3;

  const unsigned full = 0xffffffffu;
  int lane = tid & 31, w = tid >> 5;
  int sc = cnt;
#pragma unroll
  for (int off = 1; off < 32; off <<= 1) {
    int v = __shfl_up_sync(full, sc, off);
    if (lane >= off) sc += v;
  }
  if (lane == 31) wsum[w] = sc;
  __syncthreads();
  if (tid == 0) {
    int tot = 0;
#pragma unroll
    for (int i = 0; i < 8; i++) { int c = wsum[i]; wsum[i] = tot; tot += c; }
    sbase = tot ? atomicAdd(&g_counts[b], tot) : 0;
  }
  __syncthreads();

  int offs = sbase + wsum[w] + (sc - cnt);
  unsigned long long* dst = &g_cand[b * CAND_CAP];
#define RPN_EMIT(P, KEY, NN)                                                \
  if (P) {                                                                  \
    if (offs < CAND_CAP)                                                    \
      dst[offs] = ((unsigned long long)(KEY) << IDXBITS) |                  \
                  (unsigned long long)(IDXMASK - (unsigned)(NN));           \
    offs++;                                                                 \
  }
  RPN_EMIT(p0, kv.x, base)
  RPN_EMIT(p1, kv.y, base + 1)
  RPN_EMIT(p2, kv.z, base + 2)
  RPN_EMIT(p3, kv.w, base + 3)
#undef RPN_EMIT
}

// ------------------------------------------------------------------ sort ---
// PURE sort: no gather/decode tail on the 4-SM serial kernel.
typedef cub::BlockRadixSort<unsigned long long, NMS_NT, NMS_IPT,
                            cub::NullType, 6> Sorter;

__global__ __launch_bounds__(NMS_NT, 1) void sort_kernel() {
  __shared__ typename Sorter::TempStorage ts;
  const int b = blockIdx.x;
  const int tid = threadIdx.x;
  const int Creal = min(g_counts[b], CAND_CAP);

  unsigned long long tk[NMS_IPT];
#pragma unroll
  for (int i = 0; i < NMS_IPT; i++) {
    int slot = tid * NMS_IPT + i;
    tk[i] = (slot < Creal) ? g_cand[b * CAND_CAP + slot] : 0ull;
  }
  Sorter(ts).SortDescending(tk, 0, 32 + IDXBITS);
#pragma unroll
  for (int i = 0; i < NMS_IPT; i++)
    g_sorted[b * CAND_CAP + tid * NMS_IPT + i] = tk[i];
}

// ------------------------------------------------------------------ prep ---
// Wide re-decode of sorted candidates (full latency overlap across 32 blocks).
// Sentinel slots (beyond Creal) decode idx=N-1 garbage -> never read by nms.
__global__ void prep_kernel(const float4* __restrict__ anchors,
                            const float4* __restrict__ deltas,
                            const int* __restrict__ imh,
                            const int* __restrict__ imw, int N) {
  const int b = blockIdx.y;
  const int slot = blockIdx.x * blockDim.x + threadIdx.x;
  const float W = (float)(*imw);
  const float H = (float)(*imh);

  unsigned long long p = g_sorted[b * CAND_CAP + slot];
  int idx = (int)(IDXMASK - (unsigned)(p & IDXMASK));
  float4 bx = decode_box(anchors[idx], deltas[b * N + idx], W, H);
  g_cbox[b * CAND_CAP + slot] = bx;
  g_c7[b * CAND_CAP + slot] = 0.7f * ((bx.z - bx.x) * (bx.w - bx.y) + 1e-9f);
}

// ------------------------------------------------------------------ mask ---
// Upper-triangular pairwise suppression matrix. Lower-triangle words are
// never read by nms (kept rows always precede the current group) -> skip.
__global__ void mask_kernel() {
  const int w  = blockIdx.x;        // word 0..31
  const int rt = blockIdx.y;        // row tile (128 rows each)
  const int b  = blockIdx.z;
  const int tid = threadIdx.x;      // 128 threads

  if (64 * (w + 1) <= rt * 128) return;   // uniform per block: whole word < rows

  __shared__ float4 cb[64];
  __shared__ float  cc[64];
  if (tid < 64) {
    int j = w * 64 + tid;
    cb[tid] = g_cbox[b * CAND_CAP + j];
    cc[tid] = g_c7[b * CAND_CAP + j];
  }
  __syncthreads();

  const int i = rt * 128 + tid;
  float4 A = g_cbox[b * CAND_CAP + i];
  float a7 = g_c7[b * CAND_CAP + i];

  unsigned long long word = 0ull;
  int j0min = i + 1 - w * 64;       // strict j > i
  if (j0min < 0) j0min = 0;
  for (int j0 = j0min; j0 < 64; j0++) {
    float4 C = cb[j0];
    float ix1 = fmaxf(A.x, C.x), iy1 = fmaxf(A.y, C.y);
    float ix2 = fminf(A.z, C.z), iy2 = fminf(A.w, C.w);
    float inter = fmaxf(ix2 - ix1, 0.0f) * fmaxf(iy2 - iy1, 0.0f);
    if (1.7f * inter > a7 + cc[j0]) word |= 1ull << j0;
  }
  g_mask[((size_t)b * CAND_CAP + i) * WORDS + w] = word;
}

// ------------------------------------------------------------------- nms ---
struct SmemNMS {
  unsigned long long pair[GSZ];
  unsigned           warpor[16][2];
  unsigned long long s_keep;
  int                s_cnt;
};

__device__ __forceinline__ int nth_set(unsigned long long m, int r) {
  unsigned lo = (unsigned)m;
  int c = __popc(lo);
  if (r < c) return (int)__fns(lo, 0, r + 1);
  return 32 + (int)__fns((unsigned)(m >> 32), 0, r - c + 1);
}

__global__ __launch_bounds__(NMS_NT, 1) void nms_kernel(float* __restrict__ out,
                                                        int K) {
  __shared__ SmemNMS sm;
  const int b = blockIdx.x;
  const int tid = threadIdx.x;
  const int lane = tid & 31, wrp = tid >> 5;
  const unsigned full = 0xffffffffu;

  const int Creal = min(g_counts[b], CAND_CAP);
  const unsigned long long* mbase = &g_mask[(size_t)b * CAND_CAP * WORDS];

  int kp0 = -1, kp1 = -1;
  int nkept = 0, pos = 0;

  while (nkept < K && pos < Creal) {
    const int G = min(GSZ, Creal - pos);
    const int gw = pos >> 6;

    unsigned long long flags = 0ull;
    if (tid < nkept)          flags  = mbase[(size_t)kp0 * WORDS + gw];
    if (NMS_NT + tid < nkept) flags |= mbase[(size_t)kp1 * WORDS + gw];
    unsigned wlo = __reduce_or_sync(full, (unsigned)flags);
    unsigned whi = __reduce_or_sync(full, (unsigned)(flags >> 32));
    if (lane == 0) { sm.warpor[wrp][0] = wlo; sm.warpor[wrp][1] = whi; }

    if (tid < G) sm.pair[tid] = mbase[(size_t)(pos + tid) * WORDS + gw];
    __syncthreads();

    if (wrp == 0) {
      unsigned l0 = (lane < 16) ? sm.warpor[lane][0] : 0u;
      unsigned h0 = (lane < 16) ? sm.warpor[lane][1] : 0u;
      unsigned long long sup =
          (unsigned long long)__reduce_or_sync(full, l0) |
          ((unsigned long long)__reduce_or_sync(full, h0) << 32);
      unsigned long long keep = 0ull, acc = 0ull;
      int cnt = 0;
      const int room = K - nkept;
      for (int g = 0; g < G; g++) {
        bool s = (((sup | acc) >> g) & 1ull) != 0ull;
        if (!s) {
          keep |= 1ull << g;
          acc |= sm.pair[g];
          if (++cnt >= room) break;
        }
      }
      if (lane == 0) { sm.s_keep = keep; sm.s_cnt = cnt; }
    }
    __syncthreads();

    const unsigned long long keep = sm.s_keep;
    const int cnt = sm.s_cnt;
    int r0 = tid - nkept;
    if (r0 >= 0 && r0 < cnt) kp0 = pos + nth_set(keep, r0);
    int r1 = NMS_NT + tid - nkept;
    if (r1 >= 0 && r1 < cnt) kp1 = pos + nth_set(keep, r1);

    nkept += cnt;
    pos += GSZ;
    __syncthreads();
  }

  if (tid < K) {
    float* o = out + ((size_t)b * K + tid) * 6;
    if (tid < nkept) {
      float4 bx = g_cbox[b * CAND_CAP + kp0];
      unsigned key = (unsigned)(g_sorted[b * CAND_CAP + kp0] >> IDXBITS);
      unsigned bits = (key & 0x80000000u) ? (key & 0x7fffffffu) : ~key;
      o[0] = bx.x; o[1] = bx.y; o[2] = bx.z; o[3] = bx.w;
      o[4] = __uint_as_float(bits); o[5] = 1.0f;
    } else {
      o[0] = 0.0f; o[1] = 0.0f; o[2] = 0.0f; o[3] = 0.0f;
      o[4] = 0.0f; o[5] = 0.0f;
    }
  }
  int t2 = tid + NMS_NT;
  if (t2 < K) {
    float* o = out + ((size_t)b * K + t2) * 6;
    if (t2 < nkept) {
      float4 bx = g_cbox[b * CAND_CAP + kp1];
      unsigned key = (unsigned)(g_sorted[b * CAND_CAP + kp1] >> IDXBITS);
      unsigned bits = (key & 0x80000000u) ? (key & 0x7fffffffu) : ~key;
      o[0] = bx.x; o[1] = bx.y; o[2] = bx.z; o[3] = bx.w;
      o[4] = __uint_as_float(bits); o[5] = 1.0f;
    } else {
      o[0] = 0.0f; o[1] = 0.0f; o[2] = 0.0f; o[3] = 0.0f;
      o[4] = 0.0f; o[5] = 0.0f;
    }
  }
}

}  // namespace rpn

extern "C" void kernel_launch(void* const* d_in, const int* in_sizes, int n_in,
                              void* d_out, int out_size) {
  using namespace rpn;
  const float4* anchors = (const float4*)d_in[0];
  const float4* deltas  = (const float4*)d_in[1];
  const float*  obj     = (const float*)d_in[2];
  const int*    imh     = (const int*)d_in[3];
  const int*    imw     = (const int*)d_in[4];

  int N = in_sizes[0] / 4;
  int B = (N > 0) ? in_sizes[2] / N : 0;
  if (B <= 0 || N <= 0) return;
  int K = out_size / (B * 6);
  if (K > 1024) K = 1024;

  dim3 dgrid(128, B);
  decode_kernel<<<dgrid, 256>>>(anchors, deltas, obj, imh, imw, N);

  threshold_kernel<<<B, 1024>>>(SEL_TARGET);

  dim3 cgrid((N + 1023) / 1024, B);
  compact_kernel<<<cgrid, 256>>>(N);

  sort_kernel<<<B, NMS_NT>>>();

  dim3 pgrid(CAND_CAP / 256, B);
  prep_kernel<<<pgrid, 256>>>(anchors, deltas, imh, imw, N);

  dim3 mgrid(WORDS, CAND_CAP / 128, B);
  mask_kernel<<<mgrid, 128>>>();

  nms_kernel<<<B, NMS_NT>>>((float*)d_out, K);
}